// round 16
// baseline (speedup 1.0000x reference)
#include <cuda_runtime.h>
#include <cuda_fp16.h>
#include <cstdint>
#include <cstddef>

#define DINLINE __device__ __forceinline__

// Problem shape
static constexpr int N_ROWS = 4096;   // GEMM M
static constexpr int K_DIM  = 2048;   // GEMM K
static constexpr int N_OUT  = 2048;   // GEMM N

// GEMM tiling: CTA 128x128x64, 4 warps, warp tile 64x64
static constexpr int BM = 128;
static constexpr int BN = 128;
static constexpr int BK = 64;
static constexpr int STAGES = 2;                  // 2 stages -> 65.6KB smem -> 3 CTAs/SM
static constexpr int THREADS = 128;
static constexpr int KSTAGES = K_DIM / BK;        // 32

// Smem: 64 halves = 128 B/row, XOR-swizzled, no padding.
static constexpr int RSB = 128;
static constexpr int A_STAGE_B = BM * RSB;        // 16384
static constexpr int B_STAGE_B = BN * RSB;        // 16384
static constexpr int STAGE_B   = A_STAGE_B + B_STAGE_B;  // 32768
static constexpr int BAR_OFF   = STAGES * STAGE_B;       // 65536
static constexpr int SMEM_TOTAL = BAR_OFF + 64;          // 65600 (x3 CTAs/SM = 196.8KB)

// fp16 scratch (device globals: allocation-free)
__device__ __half g_Xh[(size_t)N_ROWS * K_DIM];
__device__ __half g_Wh[(size_t)N_OUT * K_DIM];

// ---------------------------------------------------------------- helpers
DINLINE uint32_t smem_u32(const void* p) {
    uint32_t a;
    asm("{ .reg .u64 t; cvta.to.shared.u64 t, %1; cvt.u32.u64 %0, t; }" : "=r"(a) : "l"(p));
    return a;
}

DINLINE void cp16(uint32_t dst, const void* src) {
    asm volatile("cp.async.cg.shared.global [%0], [%1], 16;" :: "r"(dst), "l"(src));
}

DINLINE void mbar_init(uint32_t addr, uint32_t count) {
    asm volatile("mbarrier.init.shared::cta.b64 [%0], %1;" :: "r"(addr), "r"(count) : "memory");
}

DINLINE void mbar_arrive(uint32_t addr) {
    asm volatile("mbarrier.arrive.shared::cta.b64 _, [%0];" :: "r"(addr) : "memory");
}

DINLINE void cpasync_mbar_arrive(uint32_t addr) {
    asm volatile("cp.async.mbarrier.arrive.noinc.shared::cta.b64 [%0];" :: "r"(addr) : "memory");
}

DINLINE void mbar_wait(uint32_t addr, uint32_t parity) {
    uint32_t done;
    asm volatile(
        "{\n\t.reg .pred p;\n\t"
        "mbarrier.try_wait.parity.acquire.cta.shared::cta.b64 p, [%1], %2;\n\t"
        "selp.b32 %0, 1, 0, p;\n\t}"
        : "=r"(done) : "r"(addr), "r"(parity) : "memory");
    if (!done) {
        asm volatile(
            "{\n\t.reg .pred P1;\n\t"
            "WL_%=:\n\t"
            "mbarrier.try_wait.parity.acquire.cta.shared::cta.b64 P1, [%0], %1, 0x989680;\n\t"
            "@P1 bra.uni WD_%=;\n\t"
            "bra.uni WL_%=;\n\t"
            "WD_%=:\n\t}"
            :: "r"(addr), "r"(parity) : "memory");
    }
}

DINLINE void ldmatrix_x4(uint32_t& r0, uint32_t& r1, uint32_t& r2, uint32_t& r3, uint32_t addr) {
    asm volatile("ldmatrix.sync.aligned.m8n8.x4.shared.b16 {%0, %1, %2, %3}, [%4];"
                 : "=r"(r0), "=r"(r1), "=r"(r2), "=r"(r3) : "r"(addr));
}

DINLINE void mma16816(float* d, const uint32_t* a, const uint32_t* b) {
    asm volatile(
        "mma.sync.aligned.m16n8k16.row.col.f32.f16.f16.f32 "
        "{%0, %1, %2, %3}, {%4, %5, %6, %7}, {%8, %9}, {%0, %1, %2, %3};"
        : "+f"(d[0]), "+f"(d[1]), "+f"(d[2]), "+f"(d[3])
        : "r"(a[0]), "r"(a[1]), "r"(a[2]), "r"(a[3]), "r"(b[0]), "r"(b[1]));
}

// ---------------------------------------------------------------- prep kernel
// 4096 blocks: [0,2048) input convert (4 float4/thr), [2048,4096) weight build (2 float4/thr).
__global__ void prep_kernel(const float4* __restrict__ x,
                            const float4* __restrict__ mu,
                            const float4* __restrict__ rho,
                            const float4* __restrict__ eps) {
    const int b = blockIdx.x;
    if (b < 2048) {
        size_t base = (size_t)b * 1024 + threadIdx.x;
        float4 v[4];
        #pragma unroll
        for (int i = 0; i < 4; ++i) v[i] = x[base + i * 256];
        #pragma unroll
        for (int i = 0; i < 4; ++i) {
            __align__(8) __half h[4];
            h[0] = __float2half(v[i].x); h[1] = __float2half(v[i].y);
            h[2] = __float2half(v[i].z); h[3] = __float2half(v[i].w);
            *(uint2*)(g_Xh + (base + i * 256) * 4) = *(uint2*)h;
        }
    } else {
        size_t base = (size_t)(b - 2048) * 512 + threadIdx.x;
        float4 m[2], r[2], e[2];
        #pragma unroll
        for (int i = 0; i < 2; ++i) m[i] = mu[base + i * 256];
        #pragma unroll
        for (int i = 0; i < 2; ++i) r[i] = rho[base + i * 256];
        #pragma unroll
        for (int i = 0; i < 2; ++i) e[i] = eps[base + i * 256];
        #pragma unroll
        for (int i = 0; i < 2; ++i) {
            float rr[4] = {r[i].x, r[i].y, r[i].z, r[i].w};
            float mm[4] = {m[i].x, m[i].y, m[i].z, m[i].w};
            float ee[4] = {e[i].x, e[i].y, e[i].z, e[i].w};
            __align__(8) __half h[4];
            #pragma unroll
            for (int j = 0; j < 4; ++j) {
                float sp = (rr[j] > 20.0f) ? rr[j] : log1pf(expf(rr[j]));
                h[j] = __float2half(fmaf(sp, ee[j], mm[j]));
            }
            *(uint2*)(g_Wh + (base + i * 256) * 4) = *(uint2*)h;
        }
    }
}

// ---------------------------------------------------------------- GEMM
DINLINE uint32_t swz(int row, int cc) {                 // byte offset inside a tile
    return (uint32_t)(row * RSB + ((cc ^ (row & 7)) << 4));
}

DINLINE void load_stage(int s, int tid, int m_base, int n_base, uint32_t smem_base) {
    const uint32_t sb = smem_base + (s % STAGES) * STAGE_B;
    const int kb = s * BK;
    #pragma unroll
    for (int it = 0; it < 8; ++it) {
        int c = tid + it * THREADS;           // A chunks 0..1023
        int row = c >> 3, cc = c & 7;
        const __half* g = g_Xh + (size_t)(m_base + row) * K_DIM + kb + cc * 8;
        cp16(sb + swz(row, cc), g);
    }
    #pragma unroll
    for (int it = 0; it < 8; ++it) {
        int c = tid + it * THREADS;           // B chunks 0..1023
        int row = c >> 3, cc = c & 7;
        const __half* g = g_Wh + (size_t)(n_base + row) * K_DIM + kb + cc * 8;
        cp16(sb + A_STAGE_B + swz(row, cc), g);
    }
}

// One K=16 slice of the 64x64 warp tile: 8 ldmatrix.x4 + 32 MMAs.
DINLINE void consume_ks(uint32_t sb, uint32_t sbB, int ks,
                        int arow, int brow, int ac, int bc, int r7,
                        float acc[4][8][4]) {
    uint32_t a[4][4];
    uint32_t b[8][2];
    const uint32_t akc = (uint32_t)(((ks * 2 + ac) ^ r7) << 4);
    const uint32_t bkc = (uint32_t)(((ks * 2 + bc) ^ r7) << 4);
    #pragma unroll
    for (int mi = 0; mi < 4; ++mi)
        ldmatrix_x4(a[mi][0], a[mi][1], a[mi][2], a[mi][3],
                    sb + (uint32_t)((arow + mi * 16) * RSB) + akc);
    #pragma unroll
    for (int nt = 0; nt < 4; ++nt)
        ldmatrix_x4(b[nt * 2][0], b[nt * 2][1], b[nt * 2 + 1][0], b[nt * 2 + 1][1],
                    sbB + (uint32_t)((brow + nt * 16) * RSB) + bkc);
    #pragma unroll
    for (int mi = 0; mi < 4; ++mi)
        #pragma unroll
        for (int ni = 0; ni < 8; ++ni)
            mma16816(acc[mi][ni], a[mi], b[ni]);
}

__global__ void __launch_bounds__(THREADS, 3)
gemm_kernel(const float* __restrict__ bias, float* __restrict__ out) {
    extern __shared__ char smem[];
    const uint32_t smem_base = smem_u32(smem);
    const uint32_t bar_full  = smem_base + BAR_OFF;        // full[i]  = +8*i
    const uint32_t bar_empty = smem_base + BAR_OFF + 8 * STAGES;
    const int tid  = threadIdx.x;
    const int lane = tid & 31;
    const int wid  = tid >> 5;
    const int warp_m = wid >> 1;          // 0..1 -> 64 rows each
    const int warp_n = wid & 1;           // 0..1 -> 64 cols each
    const int m_base = blockIdx.x * BM;
    const int n_base = blockIdx.y * BN;

    if (tid == 0) {
        #pragma unroll
        for (int i = 0; i < STAGES; ++i) {
            mbar_init(bar_full  + i * 8, THREADS);
            mbar_init(bar_empty + i * 8, THREADS);
        }
    }
    __syncthreads();   // one-time: barriers visible before any arrive

    float acc[4][8][4];
    #pragma unroll
    for (int mi = 0; mi < 4; ++mi)
        #pragma unroll
        for (int ni = 0; ni < 8; ++ni)
            #pragma unroll
            for (int j = 0; j < 4; ++j) acc[mi][ni][j] = 0.0f;

    // Prologue: produce stage 0
    #pragma unroll
    for (int s = 0; s < STAGES - 1; ++s) {
        load_stage(s, tid, m_base, n_base, smem_base);
        cpasync_mbar_arrive(bar_full + s * 8);
    }

    // Per-lane ldmatrix addressing (swizzled); row&7 == lane&7 for all matrices.
    const int r7   = lane & 7;
    const int arow = warp_m * 64 + (lane & 15);
    const int ac   = lane >> 4;
    const int brow = warp_n * 64 + (lane & 7) + ((lane >> 4) << 3);
    const int bc   = (lane >> 3) & 1;

    // Pipeline cursors
    int cbuf = 0, cph = 0;
    int ebuf = 0, eph = 0;

    for (int s = 0; s < KSTAGES; ++s) {
        const int t = s + STAGES - 1;                 // stage to produce
        if (t < KSTAGES) {
            if (t >= STAGES) {
                mbar_wait(bar_empty + ebuf * 8, (uint32_t)eph);
                if (++ebuf == STAGES) { ebuf = 0; eph ^= 1; }
            }
            load_stage(t, tid, m_base, n_base, smem_base);
            cpasync_mbar_arrive(bar_full + (t % STAGES) * 8);
        }

        // Consume stage s
        mbar_wait(bar_full + cbuf * 8, (uint32_t)cph);

        const uint32_t sb  = smem_base + cbuf * STAGE_B;
        const uint32_t sbB = sb + A_STAGE_B;

        #pragma unroll
        for (int ks = 0; ks < BK / 16; ++ks)
            consume_ks(sb, sbB, ks, arow, brow, ac, bc, r7, acc);

        // Release buffer
        mbar_arrive(bar_empty + cbuf * 8);
        if (++cbuf == STAGES) { cbuf = 0; cph ^= 1; }
    }

    // Epilogue: add bias, store fp32
    const int col0 = n_base + warp_n * 64;
    const int row0 = m_base + warp_m * 64;
    #pragma unroll
    for (int ni = 0; ni < 8; ++ni) {
        int o = col0 + ni * 8 + (lane & 3) * 2;
        float2 bv = *(const float2*)(bias + o);
        #pragma unroll
        for (int mi = 0; mi < 4; ++mi) {
            int r = row0 + mi * 16 + (lane >> 2);
            float2 v0 = make_float2(acc[mi][ni][0] + bv.x, acc[mi][ni][1] + bv.y);
            float2 v1 = make_float2(acc[mi][ni][2] + bv.x, acc[mi][ni][3] + bv.y);
            *(float2*)(out + (size_t)r * N_OUT + o) = v0;
            *(float2*)(out + (size_t)(r + 8) * N_OUT + o) = v1;
        }
    }
}

// ---------------------------------------------------------------- launch
extern "C" void kernel_launch(void* const* d_in, const int* in_sizes, int n_in,
                              void* d_out, int out_size) {
    const float* input = (const float*)d_in[0];
    const float* w_mu  = (const float*)d_in[1];
    const float* w_rho = (const float*)d_in[2];
    const float* w_eps = (const float*)d_in[3];
    const float* bias  = (const float*)d_in[4];
    float* out = (float*)d_out;

    cudaFuncSetAttribute(gemm_kernel, cudaFuncAttributeMaxDynamicSharedMemorySize, SMEM_TOTAL);

    prep_kernel<<<4096, 256>>>((const float4*)input, (const float4*)w_mu,
                               (const float4*)w_rho, (const float4*)w_eps);

    dim3 grid(N_ROWS / BM, N_OUT / BN, 1);   // 32 x 16 = 512 CTAs
    gemm_kernel<<<grid, THREADS, SMEM_TOTAL>>>(bias, out);
}

// round 17
// speedup vs baseline: 1.0857x; 1.0857x over previous
#include <cuda_runtime.h>
#include <cuda_fp16.h>
#include <cstdint>
#include <cstddef>

#define DINLINE __device__ __forceinline__

// Problem shape
static constexpr int N_ROWS = 4096;   // GEMM M
static constexpr int K_DIM  = 2048;   // GEMM K
static constexpr int N_OUT  = 2048;   // GEMM N

// GEMM tiling: CTA 128x128x64, 4 warps, warp tile 64x64  (R10 measured-best config)
static constexpr int BM = 128;
static constexpr int BN = 128;
static constexpr int BK = 64;
static constexpr int STAGES = 3;
static constexpr int THREADS = 128;
static constexpr int KSTAGES = K_DIM / BK;        // 32

// Smem: 64 halves = 128 B/row, XOR-swizzled, no padding.
static constexpr int RSB = 128;
static constexpr int A_STAGE_B = BM * RSB;        // 16384
static constexpr int B_STAGE_B = BN * RSB;        // 16384
static constexpr int STAGE_B   = A_STAGE_B + B_STAGE_B;  // 32768
static constexpr int BAR_OFF   = STAGES * STAGE_B;       // 98304
static constexpr int SMEM_TOTAL = BAR_OFF + 64;          // x2 CTAs/SM

// fp16 scratch (device globals: allocation-free)
__device__ __half g_Xh[(size_t)N_ROWS * K_DIM];
__device__ __half g_Wh[(size_t)N_OUT * K_DIM];

// ---------------------------------------------------------------- helpers
DINLINE uint32_t smem_u32(const void* p) {
    uint32_t a;
    asm("{ .reg .u64 t; cvta.to.shared.u64 t, %1; cvt.u32.u64 %0, t; }" : "=r"(a) : "l"(p));
    return a;
}

DINLINE void cp16(uint32_t dst, const void* src) {
    asm volatile("cp.async.cg.shared.global [%0], [%1], 16;" :: "r"(dst), "l"(src));
}

DINLINE void mbar_init(uint32_t addr, uint32_t count) {
    asm volatile("mbarrier.init.shared::cta.b64 [%0], %1;" :: "r"(addr), "r"(count) : "memory");
}

DINLINE void mbar_arrive(uint32_t addr) {
    asm volatile("mbarrier.arrive.shared::cta.b64 _, [%0];" :: "r"(addr) : "memory");
}

DINLINE void cpasync_mbar_arrive(uint32_t addr) {
    asm volatile("cp.async.mbarrier.arrive.noinc.shared::cta.b64 [%0];" :: "r"(addr) : "memory");
}

DINLINE void mbar_wait(uint32_t addr, uint32_t parity) {
    uint32_t done;
    asm volatile(
        "{\n\t.reg .pred p;\n\t"
        "mbarrier.try_wait.parity.acquire.cta.shared::cta.b64 p, [%1], %2;\n\t"
        "selp.b32 %0, 1, 0, p;\n\t}"
        : "=r"(done) : "r"(addr), "r"(parity) : "memory");
    if (!done) {
        asm volatile(
            "{\n\t.reg .pred P1;\n\t"
            "WL_%=:\n\t"
            "mbarrier.try_wait.parity.acquire.cta.shared::cta.b64 P1, [%0], %1, 0x989680;\n\t"
            "@P1 bra.uni WD_%=;\n\t"
            "bra.uni WL_%=;\n\t"
            "WD_%=:\n\t}"
            :: "r"(addr), "r"(parity) : "memory");
    }
}

DINLINE void ldmatrix_x4(uint32_t& r0, uint32_t& r1, uint32_t& r2, uint32_t& r3, uint32_t addr) {
    asm volatile("ldmatrix.sync.aligned.m8n8.x4.shared.b16 {%0, %1, %2, %3}, [%4];"
                 : "=r"(r0), "=r"(r1), "=r"(r2), "=r"(r3) : "r"(addr));
}

DINLINE void mma16816(float* d, const uint32_t* a, const uint32_t* b) {
    asm volatile(
        "mma.sync.aligned.m16n8k16.row.col.f32.f16.f16.f32 "
        "{%0, %1, %2, %3}, {%4, %5, %6, %7}, {%8, %9}, {%0, %1, %2, %3};"
        : "+f"(d[0]), "+f"(d[1]), "+f"(d[2]), "+f"(d[3])
        : "r"(a[0]), "r"(a[1]), "r"(a[2]), "r"(a[3]), "r"(b[0]), "r"(b[1]));
}

// ---------------------------------------------------------------- prep kernel
// 4096 blocks: [0,2048) input convert (4 float4/thr), [2048,4096) weight build (2 float4/thr).
__global__ void prep_kernel(const float4* __restrict__ x,
                            const float4* __restrict__ mu,
                            const float4* __restrict__ rho,
                            const float4* __restrict__ eps) {
    const int b = blockIdx.x;
    if (b < 2048) {
        size_t base = (size_t)b * 1024 + threadIdx.x;
        float4 v[4];
        #pragma unroll
        for (int i = 0; i < 4; ++i) v[i] = x[base + i * 256];
        #pragma unroll
        for (int i = 0; i < 4; ++i) {
            __align__(8) __half h[4];
            h[0] = __float2half(v[i].x); h[1] = __float2half(v[i].y);
            h[2] = __float2half(v[i].z); h[3] = __float2half(v[i].w);
            *(uint2*)(g_Xh + (base + i * 256) * 4) = *(uint2*)h;
        }
    } else {
        size_t base = (size_t)(b - 2048) * 512 + threadIdx.x;
        float4 m[2], r[2], e[2];
        #pragma unroll
        for (int i = 0; i < 2; ++i) m[i] = mu[base + i * 256];
        #pragma unroll
        for (int i = 0; i < 2; ++i) r[i] = rho[base + i * 256];
        #pragma unroll
        for (int i = 0; i < 2; ++i) e[i] = eps[base + i * 256];
        #pragma unroll
        for (int i = 0; i < 2; ++i) {
            float rr[4] = {r[i].x, r[i].y, r[i].z, r[i].w};
            float mm[4] = {m[i].x, m[i].y, m[i].z, m[i].w};
            float ee[4] = {e[i].x, e[i].y, e[i].z, e[i].w};
            __align__(8) __half h[4];
            #pragma unroll
            for (int j = 0; j < 4; ++j) {
                float sp = (rr[j] > 20.0f) ? rr[j] : log1pf(expf(rr[j]));
                h[j] = __float2half(fmaf(sp, ee[j], mm[j]));
            }
            *(uint2*)(g_Wh + (base + i * 256) * 4) = *(uint2*)h;
        }
    }
}

// ---------------------------------------------------------------- GEMM
DINLINE uint32_t swz(int row, int cc) {                 // byte offset inside a tile
    return (uint32_t)(row * RSB + ((cc ^ (row & 7)) << 4));
}

DINLINE void load_stage(int s, int tid, int m_base, int n_base, uint32_t smem_base) {
    const uint32_t sb = smem_base + (s % STAGES) * STAGE_B;
    const int kb = s * BK;
    #pragma unroll
    for (int it = 0; it < 8; ++it) {
        int c = tid + it * THREADS;           // A chunks 0..1023
        int row = c >> 3, cc = c & 7;
        const __half* g = g_Xh + (size_t)(m_base + row) * K_DIM + kb + cc * 8;
        cp16(sb + swz(row, cc), g);
    }
    #pragma unroll
    for (int it = 0; it < 8; ++it) {
        int c = tid + it * THREADS;           // B chunks 0..1023
        int row = c >> 3, cc = c & 7;
        const __half* g = g_Wh + (size_t)(n_base + row) * K_DIM + kb + cc * 8;
        cp16(sb + A_STAGE_B + swz(row, cc), g);
    }
}

// One K=16 slice of the 64x64 warp tile: 8 ldmatrix.x4 + 32 MMAs.
DINLINE void consume_ks(uint32_t sb, uint32_t sbB, int ks,
                        int arow, int brow, int ac, int bc, int r7,
                        float acc[4][8][4]) {
    uint32_t a[4][4];
    uint32_t b[8][2];
    const uint32_t akc = (uint32_t)(((ks * 2 + ac) ^ r7) << 4);
    const uint32_t bkc = (uint32_t)(((ks * 2 + bc) ^ r7) << 4);
    #pragma unroll
    for (int mi = 0; mi < 4; ++mi)
        ldmatrix_x4(a[mi][0], a[mi][1], a[mi][2], a[mi][3],
                    sb + (uint32_t)((arow + mi * 16) * RSB) + akc);
    #pragma unroll
    for (int nt = 0; nt < 4; ++nt)
        ldmatrix_x4(b[nt * 2][0], b[nt * 2][1], b[nt * 2 + 1][0], b[nt * 2 + 1][1],
                    sbB + (uint32_t)((brow + nt * 16) * RSB) + bkc);
    #pragma unroll
    for (int mi = 0; mi < 4; ++mi)
        #pragma unroll
        for (int ni = 0; ni < 8; ++ni)
            mma16816(acc[mi][ni], a[mi], b[ni]);
}

__global__ void __launch_bounds__(THREADS, 2)
gemm_kernel(const float* __restrict__ bias, float* __restrict__ out) {
    extern __shared__ char smem[];
    const uint32_t smem_base = smem_u32(smem);
    const uint32_t bar_full  = smem_base + BAR_OFF;        // full[i]  = +8*i
    const uint32_t bar_empty = smem_base + BAR_OFF + 8 * STAGES;
    const int tid  = threadIdx.x;
    const int lane = tid & 31;
    const int wid  = tid >> 5;
    const int warp_m = wid >> 1;          // 0..1 -> 64 rows each
    const int warp_n = wid & 1;           // 0..1 -> 64 cols each
    const int m_base = blockIdx.x * BM;
    const int n_base = blockIdx.y * BN;

    if (tid == 0) {
        #pragma unroll
        for (int i = 0; i < STAGES; ++i) {
            mbar_init(bar_full  + i * 8, THREADS);
            mbar_init(bar_empty + i * 8, THREADS);
        }
    }
    __syncthreads();   // one-time: barriers visible before any arrive

    // Accumulators initialized with bias (column-dependent only) — epilogue add removed.
    const int col0 = n_base + warp_n * 64;
    float acc[4][8][4];
    #pragma unroll
    for (int ni = 0; ni < 8; ++ni) {
        const float2 bv = *(const float2*)(bias + col0 + ni * 8 + (lane & 3) * 2);
        #pragma unroll
        for (int mi = 0; mi < 4; ++mi) {
            acc[mi][ni][0] = bv.x; acc[mi][ni][1] = bv.y;
            acc[mi][ni][2] = bv.x; acc[mi][ni][3] = bv.y;
        }
    }

    // Prologue: produce stages 0 and 1
    #pragma unroll
    for (int s = 0; s < STAGES - 1; ++s) {
        load_stage(s, tid, m_base, n_base, smem_base);
        cpasync_mbar_arrive(bar_full + s * 8);
    }

    // Per-lane ldmatrix addressing (swizzled); row&7 == lane&7 for all matrices.
    const int r7   = lane & 7;
    const int arow = warp_m * 64 + (lane & 15);
    const int ac   = lane >> 4;
    const int brow = warp_n * 64 + (lane & 7) + ((lane >> 4) << 3);
    const int bc   = (lane >> 3) & 1;

    // Pipeline cursors
    int cbuf = 0, cph = 0;
    int ebuf = 0, eph = 0;

    for (int s = 0; s < KSTAGES; ++s) {
        const int t = s + STAGES - 1;                 // stage to produce
        if (t < KSTAGES) {
            if (t >= STAGES) {
                mbar_wait(bar_empty + ebuf * 8, (uint32_t)eph);
                if (++ebuf == STAGES) { ebuf = 0; eph ^= 1; }
            }
            load_stage(t, tid, m_base, n_base, smem_base);
            cpasync_mbar_arrive(bar_full + (t % STAGES) * 8);
        }

        // Consume stage s
        mbar_wait(bar_full + cbuf * 8, (uint32_t)cph);

        const uint32_t sb  = smem_base + cbuf * STAGE_B;
        const uint32_t sbB = sb + A_STAGE_B;

        #pragma unroll
        for (int ks = 0; ks < BK / 16; ++ks)
            consume_ks(sb, sbB, ks, arow, brow, ac, bc, r7, acc);

        // Release buffer
        mbar_arrive(bar_empty + cbuf * 8);
        if (++cbuf == STAGES) { cbuf = 0; cph ^= 1; }
    }

    // Epilogue: store fp32 (bias already folded into acc init)
    const int row0 = m_base + warp_m * 64;
    #pragma unroll
    for (int ni = 0; ni < 8; ++ni) {
        int o = col0 + ni * 8 + (lane & 3) * 2;
        #pragma unroll
        for (int mi = 0; mi < 4; ++mi) {
            int r = row0 + mi * 16 + (lane >> 2);
            *(float2*)(out + (size_t)r * N_OUT + o) = make_float2(acc[mi][ni][0], acc[mi][ni][1]);
            *(float2*)(out + (size_t)(r + 8) * N_OUT + o) = make_float2(acc[mi][ni][2], acc[mi][ni][3]);
        }
    }
}

// ---------------------------------------------------------------- launch
extern "C" void kernel_launch(void* const* d_in, const int* in_sizes, int n_in,
                              void* d_out, int out_size) {
    const float* input = (const float*)d_in[0];
    const float* w_mu  = (const float*)d_in[1];
    const float* w_rho = (const float*)d_in[2];
    const float* w_eps = (const float*)d_in[3];
    const float* bias  = (const float*)d_in[4];
    float* out = (float*)d_out;

    cudaFuncSetAttribute(gemm_kernel, cudaFuncAttributeMaxDynamicSharedMemorySize, SMEM_TOTAL);

    prep_kernel<<<4096, 256>>>((const float4*)input, (const float4*)w_mu,
                               (const float4*)w_rho, (const float4*)w_eps);

    dim3 grid(N_ROWS / BM, N_OUT / BN, 1);   // 32 x 16 = 512 CTAs
    gemm_kernel<<<grid, THREADS, SMEM_TOTAL>>>(bias, out);
}